// round 4
// baseline (speedup 1.0000x reference)
#include <cuda_runtime.h>
#include <cuda_fp16.h>
#include <cstdint>

// ============================================================
// Problem constants
// ============================================================
#define NB 4096   // batch
#define NI 1024   // input dim
#define NO 1024   // output dim
#define K5 5      // control points per edge (j=0 basis column identically 0)
#define K4 4      // effective nonzero control points
#define KP4 (NI*K4)  // 4096 = effective GEMM reduction dim

// GEMM tiling: BM=BN=128 so 2 CTAs/SM co-reside (96KB smem, 128 regs)
#define BM 128
#define BN 128
#define BK 64
#define NSTAGE 3
#define NCHUNK (KP4/BK)         // 64

#define AS_BYTES (BM*BK*2)      // 16384
#define BS_BYTES (BN*BK*2)      // 16384
#define STAGE_BYTES (AS_BYTES + BS_BYTES)   // 32768
#define SMEM_DYN (NSTAGE*STAGE_BYTES)       // 98304

// ============================================================
// Device scratch (allocation-free rule: __device__ globals)
// ============================================================
__device__ __align__(16) __half g_A[(size_t)NB * KP4];   // [b][i*4+t] basis(j=t+1)
__device__ __align__(16) __half g_B[(size_t)NO * KP4];   // [o][i*4+t] imp*coeffs(j=t+1)

// ============================================================
// PTX helpers
// ============================================================
__device__ __forceinline__ uint32_t smem_u32(const void* p) {
    uint32_t a;
    asm("{ .reg .u64 t; cvta.to.shared.u64 t, %1; cvt.u32.u64 %0, t; }" : "=r"(a) : "l"(p));
    return a;
}
__device__ __forceinline__ void cp16(uint32_t dst, const void* src) {
    asm volatile("cp.async.cg.shared.global [%0], [%1], 16;" :: "r"(dst), "l"(src));
}
__device__ __forceinline__ void cp_commit() { asm volatile("cp.async.commit_group;"); }
template <int N> __device__ __forceinline__ void cp_wait() {
    asm volatile("cp.async.wait_group %0;" :: "n"(N));
}
__device__ __forceinline__ void ldmx4(uint32_t& r0, uint32_t& r1, uint32_t& r2, uint32_t& r3,
                                      uint32_t addr) {
    asm volatile("ldmatrix.sync.aligned.m8n8.x4.shared.b16 {%0,%1,%2,%3}, [%4];"
                 : "=r"(r0), "=r"(r1), "=r"(r2), "=r"(r3) : "r"(addr));
}
__device__ __forceinline__ void mma16816(float* c,
                                         uint32_t a0, uint32_t a1, uint32_t a2, uint32_t a3,
                                         uint32_t b0, uint32_t b1) {
    asm volatile(
        "mma.sync.aligned.m16n8k16.row.col.f32.f16.f16.f32 "
        "{%0,%1,%2,%3}, {%4,%5,%6,%7}, {%8,%9}, {%0,%1,%2,%3};"
        : "+f"(c[0]), "+f"(c[1]), "+f"(c[2]), "+f"(c[3])
        : "r"(a0), "r"(a1), "r"(a2), "r"(a3), "r"(b0), "r"(b1));
}

// ============================================================
// Fused prep kernel. W-blocks FIRST (they are the long pole; basis
// blocks backfill behind them).
//   blocks [0, NW_BLK):            w = importance*coeffs -> g_B (transposed)
//   blocks [NW_BLK, NW_BLK+NBAS):  closed-form cubic B-spline basis -> g_A
// ============================================================
#define NW_BLK  ((NI/32)*(NO/32))   // 1024
#define NBAS    ((NB*NI)/1024)      // 4096 (4 elems/thread, 256 thr)

__global__ void __launch_bounds__(256) prep_all(const float* __restrict__ x,
                                                const float* __restrict__ coeffs,
                                                const float* __restrict__ imp) {
    // w-path staging; padded rows (161, 33) => odd stride, conflict-free
    __shared__ float sc[32 * 161];   // [il][ol*5+k], row stride 161
    __shared__ float si[32 * 33];    // [il][ol],     row stride 33
    int bid = blockIdx.x;
    int tid = threadIdx.x;

    if (bid < NW_BLK) {
        // ---- w path: tile i0..i0+31 x o0..o0+31 ----
        int i0 = (bid & 31) * 32;
        int o0 = (bid >> 5) * 32;

        for (int e = tid; e < 32 * 160; e += 256) {
            int il = e / 160, r = e - il * 160;
            sc[il * 161 + r] = coeffs[((size_t)(i0 + il) * NO + o0) * K5 + r];
        }
        for (int e = tid; e < 1024; e += 256) {
            int il = e >> 5, ol = e & 31;
            si[il * 33 + ol] = imp[(size_t)(i0 + il) * NO + o0 + ol];
        }
        __syncthreads();

        // each thread: one (il, ol), 4 halves -> one 8B store.
        // warp spans il 0..31 at fixed ol -> 32 x 8B = 256B contiguous.
        for (int f = tid; f < 1024; f += 256) {
            int ol = f >> 5, il = f & 31;
            float s = si[il * 33 + ol];
            const float* cp = &sc[il * 161 + ol * 5 + 1];  // skip j=0 (always 0)
            __half2 lo = __halves2half2(__float2half(cp[0] * s), __float2half(cp[1] * s));
            __half2 hi = __halves2half2(__float2half(cp[2] * s), __float2half(cp[3] * s));
            uint2 v;
            v.x = *(uint32_t*)&lo;
            v.y = *(uint32_t*)&hi;
            *(uint2*)(g_B + (size_t)(o0 + ol) * KP4 + (size_t)(i0 + il) * 4) = v;
        }
    } else {
        // ---- basis path: 4 (b,i) elements per thread ----
        int e0 = (bid - NW_BLK) * 1024 + tid * 4;
        float4 xv = *(const float4*)(x + e0);
        float xs[4] = {xv.x, xv.y, xv.z, xv.w};
        uint4 outv[2];
        __half* hp = (__half*)outv;   // 16 halves
#pragma unroll
        for (int e = 0; e < 4; e++) {
            float xx = 4.0f * xs[e];
            float s4f = floorf(xx);
            s4f = fminf(fmaxf(s4f, 0.0f), 3.0f);
            int s4 = (int)s4f;
            float u = xx - s4f;
            float u2 = u * u, u3 = u2 * u;
            float omu = 1.0f - u;
            const float c6 = 1.0f / 6.0f;
            float v[4];
            v[0] = omu * omu * omu * c6;
            v[1] = (3.0f * u3 - 6.0f * u2 + 4.0f) * c6;
            v[2] = (-3.0f * u3 + 3.0f * u2 + 3.0f * u + 1.0f) * c6;
            v[3] = u3 * c6;
            __half h[4];
#pragma unroll
            for (int t = 0; t < 4; t++) h[t] = __float2half(0.0f);
#pragma unroll
            for (int t = 0; t < 4; t++) {
                int jm1 = s4 + t;            // basis j = s4+1+t stored at j-1
                if (jm1 < 4) h[jm1] = __float2half(v[t]);
            }
#pragma unroll
            for (int t = 0; t < 4; t++) hp[e * 4 + t] = h[t];
        }
        uint4* dst = (uint4*)(g_A + (size_t)e0 * K4);
        dst[0] = outv[0];
        dst[1] = outv[1];
    }
}

// ============================================================
// GEMM: out[4096,1024] = A[4096,4096] * B[1024,4096]^T (fp16 in, fp32 acc)
// BM=128 BN=128 BK=64, 256 threads (2x4 warps, 64x32 C per warp),
// 3-stage cp.async, xor-swizzled smem, ldmatrix.x4, 2 CTAs/SM.
// ============================================================
__global__ void __launch_bounds__(256, 2) kan_gemm(float* __restrict__ out) {
    extern __shared__ char smem[];
    const int tid = threadIdx.x;
    const int wid = tid >> 5, lane = tid & 31;
    const int wr = wid >> 2, wc = wid & 3;   // warp grid 2 (M) x 4 (N)
    const int m0 = blockIdx.x * BM, n0 = blockIdx.y * BN;

    float acc[4][4][4];
#pragma unroll
    for (int i = 0; i < 4; i++)
#pragma unroll
        for (int j = 0; j < 4; j++)
#pragma unroll
            for (int q = 0; q < 4; q++) acc[i][j][q] = 0.f;

    const uint32_t sbase = smem_u32(smem);

    auto issue = [&](int kt) {
        int s = kt % NSTAGE;
        uint32_t as = sbase + s * STAGE_BYTES;
        uint32_t bs = as + AS_BYTES;
        int koff = kt * BK;
        // A tile: 128 rows x 128B, 1024 16B chunks, 4 per thread
#pragma unroll
        for (int i = 0; i < 4; i++) {
            int ca = tid + i * 256;
            int r = ca >> 3, cc = ca & 7;
            cp16(as + r * 128 + (((cc ^ (r & 7)) << 4)),
                 g_A + (size_t)(m0 + r) * KP4 + koff + cc * 8);
        }
        // B tile: 128 rows x 128B, 4 per thread
#pragma unroll
        for (int i = 0; i < 4; i++) {
            int cb = tid + i * 256;
            int r = cb >> 3, cc = cb & 7;
            cp16(bs + r * 128 + (((cc ^ (r & 7)) << 4)),
                 g_B + (size_t)(n0 + r) * KP4 + koff + cc * 8);
        }
        cp_commit();
    };

    issue(0);
    issue(1);

    const int lrow = lane & 15;       // ldmatrix row within 16
    const int lhalf = lane >> 4;      // 16B half select
    const int lxor = lrow & 7;

    for (int kt = 0; kt < NCHUNK; kt++) {
        if (kt < NCHUNK - 1) cp_wait<1>(); else cp_wait<0>();
        __syncthreads();
        if (kt + 2 < NCHUNK) issue(kt + 2);

        int s = kt % NSTAGE;
        uint32_t as = sbase + s * STAGE_BYTES;
        uint32_t bs = as + AS_BYTES;

#pragma unroll
        for (int ks = 0; ks < 4; ks++) {
            int cc = (ks * 2 + lhalf) ^ lxor;
            uint32_t a[4][4];
#pragma unroll
            for (int mi = 0; mi < 4; mi++) {
                int r = wr * 64 + mi * 16 + lrow;
                ldmx4(a[mi][0], a[mi][1], a[mi][2], a[mi][3], as + r * 128 + cc * 16);
            }
#pragma unroll
            for (int g = 0; g < 2; g++) {
                uint32_t b0, b1, b2, b3;
                int r = wc * 32 + g * 16 + lrow;
                ldmx4(b0, b1, b2, b3, bs + r * 128 + cc * 16);
#pragma unroll
                for (int mi = 0; mi < 4; mi++) {
                    mma16816(acc[mi][g * 2 + 0], a[mi][0], a[mi][1], a[mi][2], a[mi][3], b0, b2);
                    mma16816(acc[mi][g * 2 + 1], a[mi][0], a[mi][1], a[mi][2], a[mi][3], b1, b3);
                }
            }
        }
    }

    // Epilogue: frag rows lane/4 (+8), cols 2*(lane%4)+{0,1}
    const int lr = lane >> 2;
    const int lc = (lane & 3) * 2;
#pragma unroll
    for (int mi = 0; mi < 4; mi++) {
#pragma unroll
        for (int nf = 0; nf < 4; nf++) {
            int row = m0 + wr * 64 + mi * 16 + lr;
            int col = n0 + wc * 32 + nf * 8 + lc;
            float* p = out + (size_t)row * NO + col;
            *(float2*)p = make_float2(acc[mi][nf][0], acc[mi][nf][1]);
            *(float2*)(p + 8 * NO) = make_float2(acc[mi][nf][2], acc[mi][nf][3]);
        }
    }
}

// ============================================================
// Launch
// ============================================================
extern "C" void kernel_launch(void* const* d_in, const int* in_sizes, int n_in,
                              void* d_out, int out_size) {
    const float* x = nullptr;
    const float* coeffs = nullptr;
    const float* imp = nullptr;
    for (int i = 0; i < n_in; i++) {
        if (in_sizes[i] == NB * NI) x = (const float*)d_in[i];
        else if (in_sizes[i] == NI * NO * K5) coeffs = (const float*)d_in[i];
        else if (in_sizes[i] == NI * NO) imp = (const float*)d_in[i];
    }

    prep_all<<<NW_BLK + NBAS, 256>>>(x, coeffs, imp);

    static int smem_set = 0;
    if (!smem_set) {
        cudaFuncSetAttribute(kan_gemm, cudaFuncAttributeMaxDynamicSharedMemorySize, SMEM_DYN);
        smem_set = 1;
    }
    kan_gemm<<<dim3(NB / BM, NO / BN), 256, SMEM_DYN>>>((float*)d_out);
}

// round 5
// speedup vs baseline: 1.5190x; 1.5190x over previous
#include <cuda_runtime.h>
#include <cuda_fp16.h>
#include <cstdint>

// ============================================================
// Problem constants
// ============================================================
#define NB 4096   // batch
#define NI 1024   // input dim
#define NO 1024   // output dim
#define K5 5      // control points per edge (j=0 basis column identically 0)
#define K4 4      // effective nonzero control points
#define KP4 (NI*K4)  // 4096 = effective GEMM reduction dim

// GEMM tiling (round-3 shell, 512 threads, grid 128)
#define BM 128
#define BN 256
#define BK 64
#define NSTAGE 3
#define NCHUNK (KP4/BK)         // 64

#define AS_BYTES (BM*BK*2)      // 16384
#define BS_BYTES (BN*BK*2)      // 32768
#define STAGE_BYTES (AS_BYTES + BS_BYTES)   // 49152
#define SMEM_DYN (NSTAGE*STAGE_BYTES)       // 147456

// ============================================================
// Device scratch (allocation-free rule: __device__ globals)
// ============================================================
__device__ __align__(16) __half g_A[(size_t)NB * KP4];   // [b][i*4+t] basis(j=t+1)
__device__ __align__(16) __half g_B[(size_t)NO * KP4];   // [o][i*4+t] imp*coeffs(j=t+1)

// ============================================================
// PTX helpers
// ============================================================
__device__ __forceinline__ uint32_t smem_u32(const void* p) {
    uint32_t a;
    asm("{ .reg .u64 t; cvta.to.shared.u64 t, %1; cvt.u32.u64 %0, t; }" : "=r"(a) : "l"(p));
    return a;
}
__device__ __forceinline__ void cp16(uint32_t dst, const void* src) {
    asm volatile("cp.async.cg.shared.global [%0], [%1], 16;" :: "r"(dst), "l"(src));
}
__device__ __forceinline__ void cp_commit() { asm volatile("cp.async.commit_group;"); }
template <int N> __device__ __forceinline__ void cp_wait() {
    asm volatile("cp.async.wait_group %0;" :: "n"(N));
}
__device__ __forceinline__ void ldmx4(uint32_t& r0, uint32_t& r1, uint32_t& r2, uint32_t& r3,
                                      uint32_t addr) {
    asm volatile("ldmatrix.sync.aligned.m8n8.x4.shared.b16 {%0,%1,%2,%3}, [%4];"
                 : "=r"(r0), "=r"(r1), "=r"(r2), "=r"(r3) : "r"(addr));
}
__device__ __forceinline__ void mma16816(float* c,
                                         uint32_t a0, uint32_t a1, uint32_t a2, uint32_t a3,
                                         uint32_t b0, uint32_t b1) {
    asm volatile(
        "mma.sync.aligned.m16n8k16.row.col.f32.f16.f16.f32 "
        "{%0,%1,%2,%3}, {%4,%5,%6,%7}, {%8,%9}, {%0,%1,%2,%3};"
        : "+f"(c[0]), "+f"(c[1]), "+f"(c[2]), "+f"(c[3])
        : "r"(a0), "r"(a1), "r"(a2), "r"(a3), "r"(b0), "r"(b1));
}

// ============================================================
// Kernel 1: closed-form uniform cubic B-spline basis -> g_A fp16.
// Knots linspace(-1,1,9), x in [0,1): s4 = floor(4x), u = frac(4x);
// nonzero basis j = s4+1..min(s4+4,4); zeros form a PREFIX of the 4
// stored slots: h[t] = v[t-s4] for t>=s4 else 0 -> pure selects.
// 4 elems/thread, float4 in, 2x uint4 out, no smem.
// ============================================================
__global__ void __launch_bounds__(256) prep_basis(const float* __restrict__ x) {
    int e0 = (blockIdx.x * 256 + threadIdx.x) * 4;
    float4 xv = *(const float4*)(x + e0);
    float xs[4] = {xv.x, xv.y, xv.z, xv.w};
    uint4 outv[2];
    uint32_t* wp = (uint32_t*)outv;   // 8 half2 words
#pragma unroll
    for (int e = 0; e < 4; e++) {
        float xx = 4.0f * xs[e];
        float s4f = floorf(xx);
        s4f = fminf(fmaxf(s4f, 0.0f), 3.0f);
        int s4 = (int)s4f;
        float u = xx - s4f;
        float u2 = u * u, u3 = u2 * u;
        float omu = 1.0f - u;
        const float c6 = 1.0f / 6.0f;
        float v0 = omu * omu * omu * c6;
        float v1 = (3.0f * u3 - 6.0f * u2 + 4.0f) * c6;
        float v2 = (-3.0f * u3 + 3.0f * u2 + 3.0f * u + 1.0f) * c6;
        float v3 = u3 * c6;
        // prefix-zero select: h[t] = v[t-s4] if t>=s4 else 0
        float h0 = (s4 == 0) ? v0 : 0.0f;
        float h1 = (s4 == 0) ? v1 : (s4 == 1) ? v0 : 0.0f;
        float h2 = (s4 == 0) ? v2 : (s4 == 1) ? v1 : (s4 == 2) ? v0 : 0.0f;
        float h3 = (s4 == 0) ? v3 : (s4 == 1) ? v2 : (s4 == 2) ? v1 : v0;
        __half2 p0 = __floats2half2_rn(h0, h1);
        __half2 p1 = __floats2half2_rn(h2, h3);
        wp[e * 2 + 0] = *(uint32_t*)&p0;
        wp[e * 2 + 1] = *(uint32_t*)&p1;
    }
    uint4* dst = (uint4*)(g_A + (size_t)e0 * K4);
    dst[0] = outv[0];
    dst[1] = outv[1];
}

// ============================================================
// Kernel 2: w = importance * coeffs (j=1..4), transposed to [o][i*4+t] fp16.
// 32x32 (i,o) tile; padded smem rows (161/33 floats) => conflict-free.
// ============================================================
__global__ void __launch_bounds__(256) prep_w(const float* __restrict__ coeffs,
                                              const float* __restrict__ imp) {
    __shared__ float sc[32 * 161];   // [il][ol*5+k], row stride 161
    __shared__ float si[32 * 33];    // [il][ol],     row stride 33
    int bid = blockIdx.x;
    int tid = threadIdx.x;
    int i0 = (bid & 31) * 32;
    int o0 = (bid >> 5) * 32;

    for (int e = tid; e < 32 * 160; e += 256) {
        int il = e / 160, r = e - il * 160;
        sc[il * 161 + r] = coeffs[((size_t)(i0 + il) * NO + o0) * K5 + r];
    }
    for (int e = tid; e < 1024; e += 256) {
        int il = e >> 5, ol = e & 31;
        si[il * 33 + ol] = imp[(size_t)(i0 + il) * NO + o0 + ol];
    }
    __syncthreads();

    // one (il,ol) per thread x4 passes; warp spans il at fixed ol ->
    // 32 x 8B = 256B contiguous store runs.
    for (int f = tid; f < 1024; f += 256) {
        int ol = f >> 5, il = f & 31;
        float s = si[il * 33 + ol];
        const float* cp = &sc[il * 161 + ol * 5 + 1];  // skip j=0 (always 0)
        __half2 lo = __floats2half2_rn(cp[0] * s, cp[1] * s);
        __half2 hi = __floats2half2_rn(cp[2] * s, cp[3] * s);
        uint2 v;
        v.x = *(uint32_t*)&lo;
        v.y = *(uint32_t*)&hi;
        *(uint2*)(g_B + (size_t)(o0 + ol) * KP4 + (size_t)(i0 + il) * 4) = v;
    }
}

// ============================================================
// GEMM: out[4096,1024] = A[4096,4096] * B[1024,4096]^T (fp16 in, fp32 acc)
// BM=128 BN=256 BK=64, 512 thr (4x4 warps, 32x64 C/warp), 3-stage cp.async,
// xor-swizzled smem, ldmatrix.x4, REGISTER-DOUBLE-BUFFERED fragments:
// ks+1's LDSM batch issues before ks's MMA batch (hides LDS latency).
// ============================================================
__global__ void __launch_bounds__(512, 1) kan_gemm(float* __restrict__ out) {
    extern __shared__ char smem[];
    const int tid = threadIdx.x;
    const int wid = tid >> 5, lane = tid & 31;
    const int wr = wid >> 2, wc = wid & 3;   // warp grid 4 (M) x 4 (N)
    const int m0 = blockIdx.x * BM, n0 = blockIdx.y * BN;

    float acc[2][8][4];
#pragma unroll
    for (int i = 0; i < 2; i++)
#pragma unroll
        for (int j = 0; j < 8; j++)
#pragma unroll
            for (int q = 0; q < 4; q++) acc[i][j][q] = 0.f;

    const uint32_t sbase = smem_u32(smem);

    auto issue = [&](int kt) {
        int s = kt % NSTAGE;
        uint32_t as = sbase + s * STAGE_BYTES;
        uint32_t bs = as + AS_BYTES;
        int koff = kt * BK;
#pragma unroll
        for (int i = 0; i < 2; i++) {          // A: 1024 16B chunks
            int ca = tid + i * 512;
            int r = ca >> 3, cc = ca & 7;
            cp16(as + r * 128 + (((cc ^ (r & 7)) << 4)),
                 g_A + (size_t)(m0 + r) * KP4 + koff + cc * 8);
        }
#pragma unroll
        for (int i = 0; i < 4; i++) {          // B: 2048 16B chunks
            int cb = tid + i * 512;
            int r = cb >> 3, cc = cb & 7;
            cp16(bs + r * 128 + (((cc ^ (r & 7)) << 4)),
                 g_B + (size_t)(n0 + r) * KP4 + koff + cc * 8);
        }
        cp_commit();
    };

    issue(0);
    issue(1);

    const int lrow = lane & 15;
    const int lhalf = lane >> 4;
    const int lxor = lrow & 7;

    uint32_t af[2][2][4];   // [buf][mi][reg]
    uint32_t bf[2][4][4];   // [buf][g][reg]

    for (int kt = 0; kt < NCHUNK; kt++) {
        if (kt < NCHUNK - 1) cp_wait<1>(); else cp_wait<0>();
        __syncthreads();
        if (kt + 2 < NCHUNK) issue(kt + 2);

        int s = kt % NSTAGE;
        uint32_t as = sbase + s * STAGE_BYTES;
        uint32_t bs = as + AS_BYTES;

        // prologue: frags for ks=0 into buf 0
        {
            int cc = (0 * 2 + lhalf) ^ lxor;
#pragma unroll
            for (int mi = 0; mi < 2; mi++) {
                int r = wr * 32 + mi * 16 + lrow;
                ldmx4(af[0][mi][0], af[0][mi][1], af[0][mi][2], af[0][mi][3],
                      as + r * 128 + cc * 16);
            }
#pragma unroll
            for (int g = 0; g < 4; g++) {
                int r = wc * 64 + g * 16 + lrow;
                ldmx4(bf[0][g][0], bf[0][g][1], bf[0][g][2], bf[0][g][3],
                      bs + r * 128 + cc * 16);
            }
        }

#pragma unroll
        for (int ks = 0; ks < 4; ks++) {
            int buf = ks & 1;
            if (ks < 3) {                     // prefetch next ks into other buf
                int nb = buf ^ 1;
                int cc = ((ks + 1) * 2 + lhalf) ^ lxor;
#pragma unroll
                for (int mi = 0; mi < 2; mi++) {
                    int r = wr * 32 + mi * 16 + lrow;
                    ldmx4(af[nb][mi][0], af[nb][mi][1], af[nb][mi][2], af[nb][mi][3],
                          as + r * 128 + cc * 16);
                }
#pragma unroll
                for (int g = 0; g < 4; g++) {
                    int r = wc * 64 + g * 16 + lrow;
                    ldmx4(bf[nb][g][0], bf[nb][g][1], bf[nb][g][2], bf[nb][g][3],
                          bs + r * 128 + cc * 16);
                }
            }
#pragma unroll
            for (int g = 0; g < 4; g++) {
#pragma unroll
                for (int mi = 0; mi < 2; mi++) {
                    mma16816(acc[mi][g * 2 + 0],
                             af[buf][mi][0], af[buf][mi][1], af[buf][mi][2], af[buf][mi][3],
                             bf[buf][g][0], bf[buf][g][2]);
                    mma16816(acc[mi][g * 2 + 1],
                             af[buf][mi][0], af[buf][mi][1], af[buf][mi][2], af[buf][mi][3],
                             bf[buf][g][1], bf[buf][g][3]);
                }
            }
        }
    }

    // Epilogue: frag rows lane/4 (+8), cols 2*(lane%4)+{0,1}
    const int lr = lane >> 2;
    const int lc = (lane & 3) * 2;
#pragma unroll
    for (int mi = 0; mi < 2; mi++) {
#pragma unroll
        for (int nf = 0; nf < 8; nf++) {
            int row = m0 + wr * 32 + mi * 16 + lr;
            int col = n0 + wc * 64 + nf * 8 + lc;
            float* p = out + (size_t)row * NO + col;
            *(float2*)p = make_float2(acc[mi][nf][0], acc[mi][nf][1]);
            *(float2*)(p + 8 * NO) = make_float2(acc[mi][nf][2], acc[mi][nf][3]);
        }
    }
}

// ============================================================
// Launch
// ============================================================
extern "C" void kernel_launch(void* const* d_in, const int* in_sizes, int n_in,
                              void* d_out, int out_size) {
    const float* x = nullptr;
    const float* coeffs = nullptr;
    const float* imp = nullptr;
    for (int i = 0; i < n_in; i++) {
        if (in_sizes[i] == NB * NI) x = (const float*)d_in[i];
        else if (in_sizes[i] == NI * NO * K5) coeffs = (const float*)d_in[i];
        else if (in_sizes[i] == NI * NO) imp = (const float*)d_in[i];
    }

    prep_basis<<<(NB * NI) / 1024, 256>>>(x);
    prep_w<<<(NI / 32) * (NO / 32), 256>>>(coeffs, imp);

    static int smem_set = 0;
    if (!smem_set) {
        cudaFuncSetAttribute(kan_gemm, cudaFuncAttributeMaxDynamicSharedMemorySize, SMEM_DYN);
        smem_set = 1;
    }
    kan_gemm<<<dim3(NB / BM, NO / BN), 512, SMEM_DYN>>>((float*)d_out);
}

// round 6
// speedup vs baseline: 1.5213x; 1.0015x over previous
#include <cuda_runtime.h>
#include <cuda_fp16.h>
#include <cstdint>

// ============================================================
// Problem constants
// ============================================================
#define NB 4096   // batch
#define NI 1024   // input dim
#define NO 1024   // output dim
#define K5 5      // control points per edge (j=0 basis column identically 0)
#define K4 4      // effective nonzero control points
#define KP4 (NI*K4)  // 4096 = effective GEMM reduction dim

// GEMM tiling: 512 threads, grid 128, 4-stage cp.async pipeline
#define BM 128
#define BN 256
#define BK 64
#define NSTAGE 4
#define NCHUNK (KP4/BK)         // 64

#define AS_BYTES (BM*BK*2)      // 16384
#define BS_BYTES (BN*BK*2)      // 32768
#define STAGE_BYTES (AS_BYTES + BS_BYTES)   // 49152
#define SMEM_DYN (NSTAGE*STAGE_BYTES)       // 196608

// ============================================================
// Device scratch (allocation-free rule: __device__ globals)
// ============================================================
__device__ __align__(16) __half g_A[(size_t)NB * KP4];   // [b][i*4+t] basis(j=t+1)
__device__ __align__(16) __half g_B[(size_t)NO * KP4];   // [o][i*4+t] imp*coeffs(j=t+1)

// ============================================================
// PTX helpers
// ============================================================
__device__ __forceinline__ uint32_t smem_u32(const void* p) {
    uint32_t a;
    asm("{ .reg .u64 t; cvta.to.shared.u64 t, %1; cvt.u32.u64 %0, t; }" : "=r"(a) : "l"(p));
    return a;
}
__device__ __forceinline__ void cp16(uint32_t dst, const void* src) {
    asm volatile("cp.async.cg.shared.global [%0], [%1], 16;" :: "r"(dst), "l"(src));
}
__device__ __forceinline__ void cp_commit() { asm volatile("cp.async.commit_group;"); }
template <int N> __device__ __forceinline__ void cp_wait() {
    asm volatile("cp.async.wait_group %0;" :: "n"(N));
}
__device__ __forceinline__ void ldmx4(uint32_t& r0, uint32_t& r1, uint32_t& r2, uint32_t& r3,
                                      uint32_t addr) {
    asm volatile("ldmatrix.sync.aligned.m8n8.x4.shared.b16 {%0,%1,%2,%3}, [%4];"
                 : "=r"(r0), "=r"(r1), "=r"(r2), "=r"(r3) : "r"(addr));
}
__device__ __forceinline__ void mma16816(float* c,
                                         uint32_t a0, uint32_t a1, uint32_t a2, uint32_t a3,
                                         uint32_t b0, uint32_t b1) {
    asm volatile(
        "mma.sync.aligned.m16n8k16.row.col.f32.f16.f16.f32 "
        "{%0,%1,%2,%3}, {%4,%5,%6,%7}, {%8,%9}, {%0,%1,%2,%3};"
        : "+f"(c[0]), "+f"(c[1]), "+f"(c[2]), "+f"(c[3])
        : "r"(a0), "r"(a1), "r"(a2), "r"(a3), "r"(b0), "r"(b1));
}

// ============================================================
// Kernel 1: closed-form uniform cubic B-spline basis -> g_A fp16.
// x in [0,1): s4 = floor(4x), u = frac(4x); zeros form a PREFIX of the
// 4 stored slots: h[t] = v[t-s4] for t>=s4 else 0 (pure selects).
// 8 elems/thread: 2x float4 in, 4x uint4 out.
// ============================================================
__global__ void __launch_bounds__(256) prep_basis(const float* __restrict__ x) {
    int e0 = (blockIdx.x * 256 + threadIdx.x) * 8;
    float4 xv0 = *(const float4*)(x + e0);
    float4 xv1 = *(const float4*)(x + e0 + 4);
    float xs[8] = {xv0.x, xv0.y, xv0.z, xv0.w, xv1.x, xv1.y, xv1.z, xv1.w};
    uint4 outv[4];
    uint32_t* wp = (uint32_t*)outv;   // 16 half2 words
#pragma unroll
    for (int e = 0; e < 8; e++) {
        float xx = 4.0f * xs[e];
        float s4f = floorf(xx);
        s4f = fminf(fmaxf(s4f, 0.0f), 3.0f);
        int s4 = (int)s4f;
        float u = xx - s4f;
        float u2 = u * u, u3 = u2 * u;
        float omu = 1.0f - u;
        const float c6 = 1.0f / 6.0f;
        float v0 = omu * omu * omu * c6;
        float v1 = (3.0f * u3 - 6.0f * u2 + 4.0f) * c6;
        float v2 = (-3.0f * u3 + 3.0f * u2 + 3.0f * u + 1.0f) * c6;
        float v3 = u3 * c6;
        float h0 = (s4 == 0) ? v0 : 0.0f;
        float h1 = (s4 == 0) ? v1 : (s4 == 1) ? v0 : 0.0f;
        float h2 = (s4 == 0) ? v2 : (s4 == 1) ? v1 : (s4 == 2) ? v0 : 0.0f;
        float h3 = (s4 == 0) ? v3 : (s4 == 1) ? v2 : (s4 == 2) ? v1 : v0;
        __half2 p0 = __floats2half2_rn(h0, h1);
        __half2 p1 = __floats2half2_rn(h2, h3);
        wp[e * 2 + 0] = *(uint32_t*)&p0;
        wp[e * 2 + 1] = *(uint32_t*)&p1;
    }
    uint4* dst = (uint4*)(g_A + (size_t)e0 * K4);
#pragma unroll
    for (int q = 0; q < 4; q++) dst[q] = outv[q];
}

// ============================================================
// Kernel 2: w = importance * coeffs (j=1..4), transposed to [o][i*4+t] fp16.
// 32x32 (i,o) tile; padded smem rows (161/33 floats) => conflict-free.
// ============================================================
__global__ void __launch_bounds__(256) prep_w(const float* __restrict__ coeffs,
                                              const float* __restrict__ imp) {
    __shared__ float sc[32 * 161];   // [il][ol*5+k], row stride 161
    __shared__ float si[32 * 33];    // [il][ol],     row stride 33
    int bid = blockIdx.x;
    int tid = threadIdx.x;
    int i0 = (bid & 31) * 32;
    int o0 = (bid >> 5) * 32;

    for (int e = tid; e < 32 * 160; e += 256) {
        int il = e / 160, r = e - il * 160;
        sc[il * 161 + r] = coeffs[((size_t)(i0 + il) * NO + o0) * K5 + r];
    }
    for (int e = tid; e < 1024; e += 256) {
        int il = e >> 5, ol = e & 31;
        si[il * 33 + ol] = imp[(size_t)(i0 + il) * NO + o0 + ol];
    }
    __syncthreads();

    for (int f = tid; f < 1024; f += 256) {
        int ol = f >> 5, il = f & 31;
        float s = si[il * 33 + ol];
        const float* cp = &sc[il * 161 + ol * 5 + 1];  // skip j=0 (always 0)
        __half2 lo = __floats2half2_rn(cp[0] * s, cp[1] * s);
        __half2 hi = __floats2half2_rn(cp[2] * s, cp[3] * s);
        uint2 v;
        v.x = *(uint32_t*)&lo;
        v.y = *(uint32_t*)&hi;
        *(uint2*)(g_B + (size_t)(o0 + ol) * KP4 + (size_t)(i0 + il) * 4) = v;
    }
}

// ============================================================
// GEMM: out[4096,1024] = A[4096,4096] * B[1024,4096]^T (fp16 in, fp32 acc)
// BM=128 BN=256 BK=64, 512 thr (4x4 warps, 32x64 C/warp),
// 4-stage cp.async (3 chunks in flight), xor-swizzled smem,
// register-double-buffered ldmatrix fragments.
// ============================================================
__global__ void __launch_bounds__(512, 1) kan_gemm(float* __restrict__ out) {
    extern __shared__ char smem[];
    const int tid = threadIdx.x;
    const int wid = tid >> 5, lane = tid & 31;
    const int wr = wid >> 2, wc = wid & 3;   // warp grid 4 (M) x 4 (N)
    const int m0 = blockIdx.x * BM, n0 = blockIdx.y * BN;

    float acc[2][8][4];
#pragma unroll
    for (int i = 0; i < 2; i++)
#pragma unroll
        for (int j = 0; j < 8; j++)
#pragma unroll
            for (int q = 0; q < 4; q++) acc[i][j][q] = 0.f;

    const uint32_t sbase = smem_u32(smem);

    auto issue = [&](int kt) {
        int s = kt % NSTAGE;
        uint32_t as = sbase + s * STAGE_BYTES;
        uint32_t bs = as + AS_BYTES;
        int koff = kt * BK;
#pragma unroll
        for (int i = 0; i < 2; i++) {          // A: 1024 16B chunks
            int ca = tid + i * 512;
            int r = ca >> 3, cc = ca & 7;
            cp16(as + r * 128 + (((cc ^ (r & 7)) << 4)),
                 g_A + (size_t)(m0 + r) * KP4 + koff + cc * 8);
        }
#pragma unroll
        for (int i = 0; i < 4; i++) {          // B: 2048 16B chunks
            int cb = tid + i * 512;
            int r = cb >> 3, cc = cb & 7;
            cp16(bs + r * 128 + (((cc ^ (r & 7)) << 4)),
                 g_B + (size_t)(n0 + r) * KP4 + koff + cc * 8);
        }
        cp_commit();
    };

    issue(0);
    issue(1);
    issue(2);

    const int lrow = lane & 15;
    const int lhalf = lane >> 4;
    const int lxor = lrow & 7;

    uint32_t af[2][2][4];   // [buf][mi][reg]
    uint32_t bf[2][4][4];   // [buf][g][reg]

    for (int kt = 0; kt < NCHUNK; kt++) {
        // pending chunks at loop top: kt .. min(kt+2, NCHUNK-1)
        if (kt < NCHUNK - 2) cp_wait<2>();
        else if (kt == NCHUNK - 2) cp_wait<1>();
        else cp_wait<0>();
        __syncthreads();
        if (kt + 3 < NCHUNK) issue(kt + 3);

        int s = kt % NSTAGE;
        uint32_t as = sbase + s * STAGE_BYTES;
        uint32_t bs = as + AS_BYTES;

        // prologue: frags for ks=0 into buf 0
        {
            int cc = (0 * 2 + lhalf) ^ lxor;
#pragma unroll
            for (int mi = 0; mi < 2; mi++) {
                int r = wr * 32 + mi * 16 + lrow;
                ldmx4(af[0][mi][0], af[0][mi][1], af[0][mi][2], af[0][mi][3],
                      as + r * 128 + cc * 16);
            }
#pragma unroll
            for (int g = 0; g < 4; g++) {
                int r = wc * 64 + g * 16 + lrow;
                ldmx4(bf[0][g][0], bf[0][g][1], bf[0][g][2], bf[0][g][3],
                      bs + r * 128 + cc * 16);
            }
        }

#pragma unroll
        for (int ks = 0; ks < 4; ks++) {
            int buf = ks & 1;
            if (ks < 3) {                     // prefetch next ks into other buf
                int nb = buf ^ 1;
                int cc = ((ks + 1) * 2 + lhalf) ^ lxor;
#pragma unroll
                for (int mi = 0; mi < 2; mi++) {
                    int r = wr * 32 + mi * 16 + lrow;
                    ldmx4(af[nb][mi][0], af[nb][mi][1], af[nb][mi][2], af[nb][mi][3],
                          as + r * 128 + cc * 16);
                }
#pragma unroll
                for (int g = 0; g < 4; g++) {
                    int r = wc * 64 + g * 16 + lrow;
                    ldmx4(bf[nb][g][0], bf[nb][g][1], bf[nb][g][2], bf[nb][g][3],
                          bs + r * 128 + cc * 16);
                }
            }
#pragma unroll
            for (int g = 0; g < 4; g++) {
#pragma unroll
                for (int mi = 0; mi < 2; mi++) {
                    mma16816(acc[mi][g * 2 + 0],
                             af[buf][mi][0], af[buf][mi][1], af[buf][mi][2], af[buf][mi][3],
                             bf[buf][g][0], bf[buf][g][2]);
                    mma16816(acc[mi][g * 2 + 1],
                             af[buf][mi][0], af[buf][mi][1], af[buf][mi][2], af[buf][mi][3],
                             bf[buf][g][1], bf[buf][g][3]);
                }
            }
        }
    }

    // Epilogue: frag rows lane/4 (+8), cols 2*(lane%4)+{0,1}
    const int lr = lane >> 2;
    const int lc = (lane & 3) * 2;
#pragma unroll
    for (int mi = 0; mi < 2; mi++) {
#pragma unroll
        for (int nf = 0; nf < 8; nf++) {
            int row = m0 + wr * 32 + mi * 16 + lr;
            int col = n0 + wc * 64 + nf * 8 + lc;
            float* p = out + (size_t)row * NO + col;
            *(float2*)p = make_float2(acc[mi][nf][0], acc[mi][nf][1]);
            *(float2*)(p + 8 * NO) = make_float2(acc[mi][nf][2], acc[mi][nf][3]);
        }
    }
}

// ============================================================
// Launch
// ============================================================
extern "C" void kernel_launch(void* const* d_in, const int* in_sizes, int n_in,
                              void* d_out, int out_size) {
    const float* x = nullptr;
    const float* coeffs = nullptr;
    const float* imp = nullptr;
    for (int i = 0; i < n_in; i++) {
        if (in_sizes[i] == NB * NI) x = (const float*)d_in[i];
        else if (in_sizes[i] == NI * NO * K5) coeffs = (const float*)d_in[i];
        else if (in_sizes[i] == NI * NO) imp = (const float*)d_in[i];
    }

    prep_basis<<<(NB * NI) / 2048, 256>>>(x);
    prep_w<<<(NI / 32) * (NO / 32), 256>>>(coeffs, imp);

    static int smem_set = 0;
    if (!smem_set) {
        cudaFuncSetAttribute(kan_gemm, cudaFuncAttributeMaxDynamicSharedMemorySize, SMEM_DYN);
        smem_set = 1;
    }
    kan_gemm<<<dim3(NB / BM, NO / BN), 512, SMEM_DYN>>>((float*)d_out);
}

// round 7
// speedup vs baseline: 1.5403x; 1.0125x over previous
#include <cuda_runtime.h>
#include <cuda_fp16.h>
#include <cstdint>

// ============================================================
// Problem constants
// ============================================================
#define NB 4096   // batch
#define NI 1024   // input dim
#define NO 1024   // output dim
#define K5 5      // control points per edge (j=0 basis column identically 0)
#define K4 4      // effective nonzero control points
#define KP4 (NI*K4)  // 4096 = effective GEMM reduction dim

// GEMM tiling: BM=BN=128, 256 threads, 2 CTAs/SM, 3-stage cp.async
#define BM 128
#define BN 128
#define BK 64
#define NSTAGE 3
#define NCHUNK (KP4/BK)         // 64

#define AS_BYTES (BM*BK*2)      // 16384
#define BS_BYTES (BN*BK*2)      // 16384
#define STAGE_BYTES (AS_BYTES + BS_BYTES)   // 32768
#define SMEM_DYN (NSTAGE*STAGE_BYTES)       // 98304 -> 2 CTAs/SM

// ============================================================
// Device scratch (allocation-free rule: __device__ globals)
// ============================================================
__device__ __align__(16) __half g_A[(size_t)NB * KP4];   // [b][i*4+t] basis(j=t+1)
__device__ __align__(16) __half g_B[(size_t)NO * KP4];   // [o][i*4+t] imp*coeffs(j=t+1)

// ============================================================
// PTX helpers
// ============================================================
__device__ __forceinline__ uint32_t smem_u32(const void* p) {
    uint32_t a;
    asm("{ .reg .u64 t; cvta.to.shared.u64 t, %1; cvt.u32.u64 %0, t; }" : "=r"(a) : "l"(p));
    return a;
}
__device__ __forceinline__ void cp16(uint32_t dst, const void* src) {
    asm volatile("cp.async.cg.shared.global [%0], [%1], 16;" :: "r"(dst), "l"(src));
}
__device__ __forceinline__ void cp_commit() { asm volatile("cp.async.commit_group;"); }
template <int N> __device__ __forceinline__ void cp_wait() {
    asm volatile("cp.async.wait_group %0;" :: "n"(N));
}
__device__ __forceinline__ void ldmx4(uint32_t& r0, uint32_t& r1, uint32_t& r2, uint32_t& r3,
                                      uint32_t addr) {
    asm volatile("ldmatrix.sync.aligned.m8n8.x4.shared.b16 {%0,%1,%2,%3}, [%4];"
                 : "=r"(r0), "=r"(r1), "=r"(r2), "=r"(r3) : "r"(addr));
}
__device__ __forceinline__ void mma16816(float* c,
                                         uint32_t a0, uint32_t a1, uint32_t a2, uint32_t a3,
                                         uint32_t b0, uint32_t b1) {
    asm volatile(
        "mma.sync.aligned.m16n8k16.row.col.f32.f16.f16.f32 "
        "{%0,%1,%2,%3}, {%4,%5,%6,%7}, {%8,%9}, {%0,%1,%2,%3};"
        : "+f"(c[0]), "+f"(c[1]), "+f"(c[2]), "+f"(c[3])
        : "r"(a0), "r"(a1), "r"(a2), "r"(a3), "r"(b0), "r"(b1));
}

// ============================================================
// Kernel 1: closed-form uniform cubic B-spline basis -> g_A fp16.
// (round-5 proven version: 4 elems/thread, float4 in, 2x uint4 out)
// x in [0,1): s4 = floor(4x), u = frac(4x); zeros form a PREFIX of the
// 4 stored slots: h[t] = v[t-s4] for t>=s4 else 0 (pure selects).
// ============================================================
__global__ void __launch_bounds__(256) prep_basis(const float* __restrict__ x) {
    int e0 = (blockIdx.x * 256 + threadIdx.x) * 4;
    float4 xv = *(const float4*)(x + e0);
    float xs[4] = {xv.x, xv.y, xv.z, xv.w};
    uint4 outv[2];
    uint32_t* wp = (uint32_t*)outv;   // 8 half2 words
#pragma unroll
    for (int e = 0; e < 4; e++) {
        float xx = 4.0f * xs[e];
        float s4f = floorf(xx);
        s4f = fminf(fmaxf(s4f, 0.0f), 3.0f);
        int s4 = (int)s4f;
        float u = xx - s4f;
        float u2 = u * u, u3 = u2 * u;
        float omu = 1.0f - u;
        const float c6 = 1.0f / 6.0f;
        float v0 = omu * omu * omu * c6;
        float v1 = (3.0f * u3 - 6.0f * u2 + 4.0f) * c6;
        float v2 = (-3.0f * u3 + 3.0f * u2 + 3.0f * u + 1.0f) * c6;
        float v3 = u3 * c6;
        float h0 = (s4 == 0) ? v0 : 0.0f;
        float h1 = (s4 == 0) ? v1 : (s4 == 1) ? v0 : 0.0f;
        float h2 = (s4 == 0) ? v2 : (s4 == 1) ? v1 : (s4 == 2) ? v0 : 0.0f;
        float h3 = (s4 == 0) ? v3 : (s4 == 1) ? v2 : (s4 == 2) ? v1 : v0;
        __half2 p0 = __floats2half2_rn(h0, h1);
        __half2 p1 = __floats2half2_rn(h2, h3);
        wp[e * 2 + 0] = *(uint32_t*)&p0;
        wp[e * 2 + 1] = *(uint32_t*)&p1;
    }
    uint4* dst = (uint4*)(g_A + (size_t)e0 * K4);
    dst[0] = outv[0];
    dst[1] = outv[1];
}

// ============================================================
// Kernel 2: w = importance * coeffs (j=1..4), transposed to [o][i*4+t] fp16.
// 32x32 (i,o) tile; padded smem rows (161/33 floats) => conflict-free.
// ============================================================
__global__ void __launch_bounds__(256) prep_w(const float* __restrict__ coeffs,
                                              const float* __restrict__ imp) {
    __shared__ float sc[32 * 161];   // [il][ol*5+k], row stride 161
    __shared__ float si[32 * 33];    // [il][ol],     row stride 33
    int bid = blockIdx.x;
    int tid = threadIdx.x;
    int i0 = (bid & 31) * 32;
    int o0 = (bid >> 5) * 32;

    for (int e = tid; e < 32 * 160; e += 256) {
        int il = e / 160, r = e - il * 160;
        sc[il * 161 + r] = coeffs[((size_t)(i0 + il) * NO + o0) * K5 + r];
    }
    for (int e = tid; e < 1024; e += 256) {
        int il = e >> 5, ol = e & 31;
        si[il * 33 + ol] = imp[(size_t)(i0 + il) * NO + o0 + ol];
    }
    __syncthreads();

    for (int f = tid; f < 1024; f += 256) {
        int ol = f >> 5, il = f & 31;
        float s = si[il * 33 + ol];
        const float* cp = &sc[il * 161 + ol * 5 + 1];  // skip j=0 (always 0)
        __half2 lo = __floats2half2_rn(cp[0] * s, cp[1] * s);
        __half2 hi = __floats2half2_rn(cp[2] * s, cp[3] * s);
        uint2 v;
        v.x = *(uint32_t*)&lo;
        v.y = *(uint32_t*)&hi;
        *(uint2*)(g_B + (size_t)(o0 + ol) * KP4 + (size_t)(i0 + il) * 4) = v;
    }
}

// ============================================================
// GEMM: out[4096,1024] = A[4096,4096] * B[1024,4096]^T (fp16 in, fp32 acc)
// BM=128 BN=128 BK=64, 256 thr (4x2 warps, 32x64 C/warp = same inner
// loop as round 5), 3-stage cp.async, xor-swizzled smem,
// register-double-buffered ldmatrix fragments, 2 CTAs/SM.
// ============================================================
__global__ void __launch_bounds__(256, 2) kan_gemm(float* __restrict__ out) {
    extern __shared__ char smem[];
    const int tid = threadIdx.x;
    const int wid = tid >> 5, lane = tid & 31;
    const int wr = wid >> 1, wc = wid & 1;   // warp grid 4 (M) x 2 (N)
    const int m0 = blockIdx.x * BM, n0 = blockIdx.y * BN;

    float acc[2][8][4];
#pragma unroll
    for (int i = 0; i < 2; i++)
#pragma unroll
        for (int j = 0; j < 8; j++)
#pragma unroll
            for (int q = 0; q < 4; q++) acc[i][j][q] = 0.f;

    const uint32_t sbase = smem_u32(smem);

    auto issue = [&](int kt) {
        int s = kt % NSTAGE;
        uint32_t as = sbase + s * STAGE_BYTES;
        uint32_t bs = as + AS_BYTES;
        int koff = kt * BK;
#pragma unroll
        for (int i = 0; i < 2; i++) {          // A: 512 16B chunks
            int ca = tid + i * 256;
            int r = ca >> 2, cc = ca & 3;      // wait: 128 rows x 8 chunks...
            // NOTE: 128 rows x 8 chunks of 16B = 1024 chunks; with 256 thr
            // we need 4 per tile. Use 4 iters below instead.
            (void)r; (void)cc;
        }
        // A tile: 128 rows x 128B = 1024 16B chunks, 4 per thread
#pragma unroll
        for (int i = 0; i < 4; i++) {
            int ca = tid + i * 256;
            int r = ca >> 3, cc = ca & 7;
            cp16(as + r * 128 + (((cc ^ (r & 7)) << 4)),
                 g_A + (size_t)(m0 + r) * KP4 + koff + cc * 8);
        }
        // B tile: 128 rows x 128B = 1024 16B chunks, 4 per thread
#pragma unroll
        for (int i = 0; i < 4; i++) {
            int cb = tid + i * 256;
            int r = cb >> 3, cc = cb & 7;
            cp16(bs + r * 128 + (((cc ^ (r & 7)) << 4)),
                 g_B + (size_t)(n0 + r) * KP4 + koff + cc * 8);
        }
        cp_commit();
    };

    issue(0);
    issue(1);

    const int lrow = lane & 15;
    const int lhalf = lane >> 4;
    const int lxor = lrow & 7;

    uint32_t af[2][2][4];   // [buf][mi][reg]
    uint32_t bf[2][4][4];   // [buf][g][reg]

    for (int kt = 0; kt < NCHUNK; kt++) {
        if (kt < NCHUNK - 1) cp_wait<1>(); else cp_wait<0>();
        __syncthreads();
        if (kt + 2 < NCHUNK) issue(kt + 2);

        int s = kt % NSTAGE;
        uint32_t as = sbase + s * STAGE_BYTES;
        uint32_t bs = as + AS_BYTES;

        // prologue: frags for ks=0 into buf 0
        {
            int cc = (0 * 2 + lhalf) ^ lxor;
#pragma unroll
            for (int mi = 0; mi < 2; mi++) {
                int r = wr * 32 + mi * 16 + lrow;
                ldmx4(af[0][mi][0], af[0][mi][1], af[0][mi][2], af[0][mi][3],
                      as + r * 128 + cc * 16);
            }
#pragma unroll
            for (int g = 0; g < 4; g++) {
                int r = wc * 64 + g * 16 + lrow;
                ldmx4(bf[0][g][0], bf[0][g][1], bf[0][g][2], bf[0][g][3],
                      bs + r * 128 + cc * 16);
            }
        }

#pragma unroll
        for (int ks = 0; ks < 4; ks++) {
            int buf = ks & 1;
            if (ks < 3) {                     // prefetch next ks into other buf
                int nb = buf ^ 1;
                int cc = ((ks + 1) * 2 + lhalf) ^ lxor;
#pragma unroll
                for (int mi = 0; mi < 2; mi++) {
                    int r = wr * 32 + mi * 16 + lrow;
                    ldmx4(af[nb][mi][0], af[nb][mi][1], af[nb][mi][2], af[nb][mi][3],
                          as + r * 128 + cc * 16);
                }
#pragma unroll
                for (int g = 0; g < 4; g++) {
                    int r = wc * 64 + g * 16 + lrow;
                    ldmx4(bf[nb][g][0], bf[nb][g][1], bf[nb][g][2], bf[nb][g][3],
                          bs + r * 128 + cc * 16);
                }
            }
#pragma unroll
            for (int g = 0; g < 4; g++) {
#pragma unroll
                for (int mi = 0; mi < 2; mi++) {
                    mma16816(acc[mi][g * 2 + 0],
                             af[buf][mi][0], af[buf][mi][1], af[buf][mi][2], af[buf][mi][3],
                             bf[buf][g][0], bf[buf][g][2]);
                    mma16816(acc[mi][g * 2 + 1],
                             af[buf][mi][0], af[buf][mi][1], af[buf][mi][2], af[buf][mi][3],
                             bf[buf][g][1], bf[buf][g][3]);
                }
            }
        }
    }

    // Epilogue: frag rows lane/4 (+8), cols 2*(lane%4)+{0,1}
    const int lr = lane >> 2;
    const int lc = (lane & 3) * 2;
#pragma unroll
    for (int mi = 0; mi < 2; mi++) {
#pragma unroll
        for (int nf = 0; nf < 8; nf++) {
            int row = m0 + wr * 32 + mi * 16 + lr;
            int col = n0 + wc * 64 + nf * 8 + lc;
            float* p = out + (size_t)row * NO + col;
            *(float2*)p = make_float2(acc[mi][nf][0], acc[mi][nf][1]);
            *(float2*)(p + 8 * NO) = make_float2(acc[mi][nf][2], acc[mi][nf][3]);
        }
    }
}

// ============================================================
// Launch
// ============================================================
extern "C" void kernel_launch(void* const* d_in, const int* in_sizes, int n_in,
                              void* d_out, int out_size) {
    const float* x = nullptr;
    const float* coeffs = nullptr;
    const float* imp = nullptr;
    for (int i = 0; i < n_in; i++) {
        if (in_sizes[i] == NB * NI) x = (const float*)d_in[i];
        else if (in_sizes[i] == NI * NO * K5) coeffs = (const float*)d_in[i];
        else if (in_sizes[i] == NI * NO) imp = (const float*)d_in[i];
    }

    prep_basis<<<(NB * NI) / 1024, 256>>>(x);
    prep_w<<<(NI / 32) * (NO / 32), 256>>>(coeffs, imp);

    static int smem_set = 0;
    if (!smem_set) {
        cudaFuncSetAttribute(kan_gemm, cudaFuncAttributeMaxDynamicSharedMemorySize, SMEM_DYN);
        smem_set = 1;
    }
    kan_gemm<<<dim3(NB / BM, NO / BN), 256, SMEM_DYN>>>((float*)d_out);
}